// round 4
// baseline (speedup 1.0000x reference)
#include <cuda_runtime.h>
#include <math.h>
#include <stdint.h>

#define THREADS   256
#define IMGS      128          // images per block, 1 per thread (x2 col-halves)
#define NP        129          // float4 stride per v-row (odd -> conflict-free)
#define PX_F4     (14 * NP)    // 1806 float4 per pixel buffer
#define W_FLOATS  7840
#define SMEM_FLOATS (2 * PX_F4 * 4 + W_FLOATS + 16)   // 22304 floats = 89.2 KB

typedef unsigned long long ull;

__device__ __forceinline__ void fma2(ull &acc, ull a, ull b) {
    asm("fma.rn.f32x2 %0, %1, %2, %0;" : "+l"(acc) : "l"(a), "l"(b));
}
__device__ __forceinline__ ull pack2(float lo, float hi) {
    ull r; asm("mov.b64 %0, {%1, %2};" : "=l"(r) : "f"(lo), "f"(hi)); return r;
}
__device__ __forceinline__ float2 unpack2(ull v) {
    float lo, hi; asm("mov.b64 {%0, %1}, %2;" : "=f"(lo), "=f"(hi) : "l"(v));
    return make_float2(lo, hi);
}
__device__ __forceinline__ uint32_t smem_u32(const void* p) {
    uint32_t a;
    asm("{ .reg .u64 t; cvta.to.shared.u64 t, %1; cvt.u32.u64 %0, t; }" : "=r"(a) : "l"(p));
    return a;
}
__device__ __forceinline__ void cp16(uint32_t dst, const float* src) {
    asm volatile("cp.async.cg.shared.global [%0], [%1], 16;" :: "r"(dst), "l"(src));
}

// one patch-row tile, one image, cols CB..CB+6 (per-column compile-time parity)
template<int CB>
__device__ __forceinline__ void compute_tile(const float4* __restrict__ px,
                                             const float*  __restrict__ s_W,
                                             int r, int img, ull* acc)
{
    const ulonglong2* wbase = (const ulonglong2*)s_W + r * 14;
    #pragma unroll
    for (int cc = 0; cc < 7; cc++) {
        const int c  = CB + cc;       // compile-time
        const int vA = c >> 1;        // float4 holding pixels 4vA..4vA+3 of row 2r
        const int vB = 7 + vA;        // row 2r+1
        float4 a = px[vA * NP + img];   // CSE'd across cc sharing vA
        float4 b = px[vB * NP + img];
        float x0, x1, x2, x3;
        if ((c & 1) == 0) { x0 = a.x; x1 = a.y; x2 = b.x; x3 = b.y; }
        else              { x0 = a.z; x1 = a.w; x2 = b.z; x3 = b.w; }
        float e0 = __cosf(x0);
        float e1 = e0 * __cosf(x1);
        float e2 = e1 * __cosf(x2);
        float e3 = e2 * __cosf(x3);
        ull e01 = pack2(e0, e1), e23 = pack2(e2, e3);
        const ulonglong2* wrow = wbase + c;
        #pragma unroll
        for (int o = 0; o < 10; o++) {
            ulonglong2 w = wrow[o * 196];    // uniform LDS.128 broadcast
            fma2(acc[o], e01, w.x);
            fma2(acc[o], e23, w.y);
        }
    }
}

__global__ void __launch_bounds__(THREADS, 2)
quanv_kernel(const float* __restrict__ x,
             const float* __restrict__ W,
             const float* __restrict__ b,
             float* __restrict__ out)
{
    extern __shared__ float smem[];
    float4* px4 = (float4*)smem;                       // two buffers of PX_F4
    float*  s_W = smem + 2 * PX_F4 * 4;                // 7840 floats (16B aligned)
    float*  s_b = s_W + W_FLOATS;
    float*  s_mg = smem;                               // merge buffer aliases buffer 0

    const int tid   = threadIdx.x;
    const int img   = tid & 127;      // image slot
    const int chalf = tid >> 7;       // 0: cols 0..6, 1: cols 7..13 (warp-group uniform)

    const long imgBase = (long)blockIdx.x * IMGS;
    const float* xg = x + imgBase * 784;
    const uint32_t smem_base = smem_u32(smem);

    // staging offsets (7 cp.async of 16B per thread per tile)
    int srcF[7];
    uint32_t dstB[7];
    #pragma unroll
    for (int it = 0; it < 7; it++) {
        int j = tid + it * THREADS;     // 0..1791 = 128 imgs x 14 vec4
        int im = j / 14;
        int v  = j - im * 14;
        srcF[it] = im * 784 + v * 4;
        dstB[it] = (uint32_t)(v * NP + im) * 16u;
    }

    // W (+ b) into shared
    {
        const float4* Wg = (const float4*)W;
        float4* Ws = (float4*)s_W;
        #pragma unroll 4
        for (int i = tid; i < W_FLOATS / 4; i += THREADS) Ws[i] = Wg[i];
        if (tid < 10) s_b[tid] = b[tid];
    }

    // issue tile 0
    #pragma unroll
    for (int it = 0; it < 7; it++) cp16(smem_base + dstB[it], xg + srcF[it]);
    asm volatile("cp.async.commit_group;" ::: "memory");

    ull acc[10];
    #pragma unroll
    for (int o = 0; o < 10; o++) acc[o] = 0ull;

    #pragma unroll 1
    for (int r = 0; r < 14; r++) {
        if (r < 13) {
            uint32_t bufB = smem_base + ((uint32_t)((r + 1) & 1)) * (PX_F4 * 16u);
            const float* srcT = xg + (r + 1) * 56;
            #pragma unroll
            for (int it = 0; it < 7; it++) cp16(bufB + dstB[it], srcT + srcF[it]);
            asm volatile("cp.async.commit_group;" ::: "memory");
            asm volatile("cp.async.wait_group 1;" ::: "memory");
        } else {
            asm volatile("cp.async.wait_group 0;" ::: "memory");
        }
        __syncthreads();

        const float4* px = px4 + (r & 1) * PX_F4;
        if (chalf == 0) compute_tile<0>(px, s_W, r, img, acc);
        else            compute_tile<7>(px, s_W, r, img, acc);
        __syncthreads();
    }

    // reduce f32x2 (even/odd k) lanes
    float sA[10];
    #pragma unroll
    for (int o = 0; o < 10; o++) {
        float2 a = unpack2(acc[o]);
        sA[o] = a.x + a.y;
    }

    // merge column-halves via shared (stride 11 -> conflict-light)
    if (chalf == 1) {
        #pragma unroll
        for (int o = 0; o < 10; o++) s_mg[img * 11 + o] = sA[o];
    }
    __syncthreads();

    if (chalf == 0) {
        float l[10];
        float m = -INFINITY;
        #pragma unroll
        for (int o = 0; o < 10; o++) {
            l[o] = sA[o] + s_mg[img * 11 + o] + s_b[o];
            m = fmaxf(m, l[o]);
        }
        float s = 0.f;
        #pragma unroll
        for (int o = 0; o < 10; o++) s += __expf(l[o] - m);
        float lse = m + __logf(s);
        float* op = out + (imgBase + img) * 10;
        #pragma unroll
        for (int o = 0; o < 10; o++) op[o] = l[o] - lse;
    }
}

extern "C" void kernel_launch(void* const* d_in, const int* in_sizes, int n_in,
                              void* d_out, int out_size)
{
    const float* x = (const float*)d_in[0];
    const float* W = (const float*)d_in[1];
    const float* b = (const float*)d_in[2];
    float* out = (float*)d_out;

    const int B = in_sizes[0] / 784;                 // 65536
    const int grid = B / IMGS;                       // 512
    const size_t smem = SMEM_FLOATS * sizeof(float); // ~89.2 KB

    cudaFuncSetAttribute(quanv_kernel,
                         cudaFuncAttributeMaxDynamicSharedMemorySize, (int)smem);
    quanv_kernel<<<grid, THREADS, smem>>>(x, W, b, out);
}

// round 5
// speedup vs baseline: 1.0196x; 1.0196x over previous
#include <cuda_runtime.h>
#include <math.h>
#include <stdint.h>

#define THREADS   256
#define IMGS      128
#define NP        129                       // float4 stride per v-row
#define PX_BYTES  (14 * NP * 16)            // 28896 B per pixel buffer
#define WT_BYTES  (140 * 16)                // 2240 B per W tile buffer (10 o x 14 granules)
#define SMEM_BYTES (2 * PX_BYTES + 2 * WT_BYTES + 64)   // ~62.4 KB

typedef unsigned long long ull;

__device__ __forceinline__ void fma2(ull &acc, ull a, ull b) {
    asm("fma.rn.f32x2 %0, %1, %2, %0;" : "+l"(acc) : "l"(a), "l"(b));
}
__device__ __forceinline__ ull pack2(float lo, float hi) {
    ull r; asm("mov.b64 %0, {%1, %2};" : "=l"(r) : "f"(lo), "f"(hi)); return r;
}
__device__ __forceinline__ float2 unpack2(ull v) {
    float lo, hi; asm("mov.b64 {%0, %1}, %2;" : "=f"(lo), "=f"(hi) : "l"(v));
    return make_float2(lo, hi);
}
__device__ __forceinline__ uint32_t smem_u32(const void* p) {
    uint32_t a;
    asm("{ .reg .u64 t; cvta.to.shared.u64 t, %1; cvt.u32.u64 %0, t; }" : "=r"(a) : "l"(p));
    return a;
}
__device__ __forceinline__ void cp16(uint32_t dst, const float* src) {
    asm volatile("cp.async.cg.shared.global [%0], [%1], 16;" :: "r"(dst), "l"(src));
}

// one patch-row tile, one image, cols CB..CB+6 (compile-time parity select)
template<int CB>
__device__ __forceinline__ void compute_tile(const float4* __restrict__ px,
                                             const ulonglong2* __restrict__ wt,
                                             int img, ull* acc)
{
    #pragma unroll
    for (int cc = 0; cc < 7; cc++) {
        const int c  = CB + cc;       // compile-time
        const int vA = c >> 1;        // float4 with pixels 4vA..4vA+3 of row 2r
        const int vB = 7 + vA;        // row 2r+1
        float4 a = px[vA * NP + img];   // CSE across cc sharing vA
        float4 b = px[vB * NP + img];
        float x0, x1, x2, x3;
        if ((c & 1) == 0) { x0 = a.x; x1 = a.y; x2 = b.x; x3 = b.y; }
        else              { x0 = a.z; x1 = a.w; x2 = b.z; x3 = b.w; }
        float e0 = __cosf(x0);
        float e1 = e0 * __cosf(x1);
        float e2 = e1 * __cosf(x2);
        float e3 = e2 * __cosf(x3);
        ull e01 = pack2(e0, e1), e23 = pack2(e2, e3);
        #pragma unroll
        for (int o = 0; o < 10; o++) {
            ulonglong2 w = wt[o * 14 + c];   // uniform LDS.128 broadcast
            fma2(acc[o], e01, w.x);
            fma2(acc[o], e23, w.y);
        }
    }
}

__global__ void __launch_bounds__(THREADS, 3)
quanv_kernel(const float* __restrict__ x,
             const float* __restrict__ W,
             const float* __restrict__ b,
             float* __restrict__ out)
{
    extern __shared__ char smem[];
    float* s_mg = (float*)smem;                               // epilogue merge (aliases px0)
    float* s_b  = (float*)(smem + 2 * PX_BYTES + 2 * WT_BYTES);

    const int tid   = threadIdx.x;
    const int img   = tid & 127;
    const int chalf = tid >> 7;       // 0: cols 0..6, 1: cols 7..13

    const long imgBase = (long)blockIdx.x * IMGS;
    const float* xg = x + imgBase * 784;

    const uint32_t base = smem_u32(smem);
    const uint32_t PX0 = base, PX1 = base + PX_BYTES;
    const uint32_t WT0 = base + 2 * PX_BYTES, WT1 = WT0 + WT_BYTES;

    // pixel granule offsets (r-invariant)
    int      srcF[7];
    uint32_t pdst[7];
    #pragma unroll
    for (int it = 0; it < 7; it++) {
        int j  = tid + it * THREADS;      // 0..1791 = 128 imgs x 14 vec4
        int im = j / 14;
        int v  = j - im * 14;
        srcF[it] = im * 784 + v * 4;      // + r*56 per tile
        pdst[it] = (uint32_t)(v * NP + im) * 16u;
    }
    // W granule: tid < 140 -> o = tid/14, h = tid%14 ; dst = tid*16 (coalesced)
    const int wo = tid / 14, wh = tid - wo * 14;
    const int wsrc = wo * 784 + wh * 4;   // + r*56 per tile

    if (tid < 10) s_b[tid] = b[tid];

    // issue tile 0 (pixels + W) as one group
    #pragma unroll
    for (int it = 0; it < 7; it++) cp16(PX0 + pdst[it], xg + srcF[it]);
    if (tid < 140) cp16(WT0 + (uint32_t)tid * 16u, W + wsrc);
    asm volatile("cp.async.commit_group;" ::: "memory");

    ull acc[10];
    #pragma unroll
    for (int o = 0; o < 10; o++) acc[o] = 0ull;

    #pragma unroll 1
    for (int r = 0; r < 14; r++) {
        if (r < 13) {
            const uint32_t pb = ((r + 1) & 1) ? PX1 : PX0;
            const uint32_t wb = ((r + 1) & 1) ? WT1 : WT0;
            const float* srcT = xg + (r + 1) * 56;
            #pragma unroll
            for (int it = 0; it < 7; it++) cp16(pb + pdst[it], srcT + srcF[it]);
            if (tid < 140) cp16(wb + (uint32_t)tid * 16u, W + (r + 1) * 56 + wsrc);
            asm volatile("cp.async.commit_group;" ::: "memory");
            asm volatile("cp.async.wait_group 1;" ::: "memory");
        } else {
            asm volatile("cp.async.wait_group 0;" ::: "memory");
        }
        __syncthreads();

        const float4*     px = (const float4*)(smem + (r & 1) * PX_BYTES);
        const ulonglong2* wt = (const ulonglong2*)(smem + 2 * PX_BYTES + (r & 1) * WT_BYTES);
        if (chalf == 0) compute_tile<0>(px, wt, img, acc);
        else            compute_tile<7>(px, wt, img, acc);
        __syncthreads();
    }

    // reduce f32x2 lanes
    float sA[10];
    #pragma unroll
    for (int o = 0; o < 10; o++) {
        float2 a = unpack2(acc[o]);
        sA[o] = a.x + a.y;
    }

    // merge column-halves via shared (stride 11)
    if (chalf == 1) {
        #pragma unroll
        for (int o = 0; o < 10; o++) s_mg[img * 11 + o] = sA[o];
    }
    __syncthreads();

    if (chalf == 0) {
        float l[10];
        float m = -INFINITY;
        #pragma unroll
        for (int o = 0; o < 10; o++) {
            l[o] = sA[o] + s_mg[img * 11 + o] + s_b[o];
            m = fmaxf(m, l[o]);
        }
        float s = 0.f;
        #pragma unroll
        for (int o = 0; o < 10; o++) s += __expf(l[o] - m);
        float lse = m + __logf(s);
        float* op = out + (imgBase + img) * 10;
        #pragma unroll
        for (int o = 0; o < 10; o++) op[o] = l[o] - lse;
    }
}

extern "C" void kernel_launch(void* const* d_in, const int* in_sizes, int n_in,
                              void* d_out, int out_size)
{
    const float* x = (const float*)d_in[0];
    const float* W = (const float*)d_in[1];
    const float* b = (const float*)d_in[2];
    float* out = (float*)d_out;

    const int B = in_sizes[0] / 784;                 // 65536
    const int grid = B / IMGS;                       // 512

    cudaFuncSetAttribute(quanv_kernel,
                         cudaFuncAttributeMaxDynamicSharedMemorySize, SMEM_BYTES);
    quanv_kernel<<<grid, THREADS, SMEM_BYTES>>>(x, W, b, out);
}

// round 6
// speedup vs baseline: 1.2842x; 1.2594x over previous
#include <cuda_runtime.h>
#include <math.h>
#include <stdint.h>

#define THREADS   256
#define IMGS      128
#define NP        129                        // float4 stride per v-row (odd)
#define PX_F4     (14 * NP)                  // 1806 float4, single buffer
#define W_FLOATS  7840
#define SMEM_FLOATS (PX_F4 * 4 + W_FLOATS + 16)   // 15080 floats = 60.3 KB

typedef unsigned long long ull;

__device__ __forceinline__ void fma2(ull &acc, ull a, ull b) {
    asm("fma.rn.f32x2 %0, %1, %2, %0;" : "+l"(acc) : "l"(a), "l"(b));
}
__device__ __forceinline__ ull pack2(float lo, float hi) {
    ull r; asm("mov.b64 %0, {%1, %2};" : "=l"(r) : "f"(lo), "f"(hi)); return r;
}
__device__ __forceinline__ float2 unpack2(ull v) {
    float lo, hi; asm("mov.b64 {%0, %1}, %2;" : "=f"(lo), "=f"(hi) : "l"(v));
    return make_float2(lo, hi);
}

// one patch-row tile, one image, cols CB..CB+6 (compile-time parity select)
template<int CB>
__device__ __forceinline__ void compute_tile(const float4* __restrict__ px,
                                             const float*  __restrict__ s_W,
                                             int r, int img, ull* acc)
{
    const ulonglong2* wbase = (const ulonglong2*)s_W + r * 14;
    #pragma unroll
    for (int cc = 0; cc < 7; cc++) {
        const int c  = CB + cc;        // compile-time
        const int vA = c >> 1;         // float4 with pixels 4vA..4vA+3 of row 2r
        const int vB = 7 + vA;         // row 2r+1
        float4 a = px[vA * NP + img];  // CSE'd across the two cols sharing vA
        float4 b = px[vB * NP + img];
        float x0, x1, x2, x3;
        if ((c & 1) == 0) { x0 = a.x; x1 = a.y; x2 = b.x; x3 = b.y; }
        else              { x0 = a.z; x1 = a.w; x2 = b.z; x3 = b.w; }
        float e0 = __cosf(x0);
        float e1 = e0 * __cosf(x1);
        float e2 = e1 * __cosf(x2);
        float e3 = e2 * __cosf(x3);
        ull e01 = pack2(e0, e1), e23 = pack2(e2, e3);
        const ulonglong2* wrow = wbase + c;
        #pragma unroll
        for (int o = 0; o < 10; o++) {
            ulonglong2 w = wrow[o * 196];    // uniform LDS.128 broadcast
            fma2(acc[o], e01, w.x);
            fma2(acc[o], e23, w.y);
        }
    }
}

__global__ void __launch_bounds__(THREADS)
quanv_kernel(const float* __restrict__ x,
             const float* __restrict__ W,
             const float* __restrict__ b,
             float* __restrict__ out)
{
    extern __shared__ float smem[];
    float4* s_px = (float4*)smem;              // [14][NP] float4, single buffer
    float*  s_W  = smem + PX_F4 * 4;           // 7840 floats
    float*  s_b  = s_W + W_FLOATS;
    float*  s_mg = smem;                       // epilogue merge aliases px buffer

    const int tid  = threadIdx.x;
    const int lane = tid & 31;
    const int warp = tid >> 5;
    const int img   = (warp & 3) * 32 + lane;  // 0..127
    const int chalf = warp >> 2;               // 0: cols 0..6, 1: cols 7..13

    const long imgBase = (long)blockIdx.x * IMGS;
    const float* xg = x + imgBase * 784;

    // staging map (r-invariant): 7 float4 granules per thread
    int srcF[7], dstI[7];
    #pragma unroll
    for (int it = 0; it < 7; it++) {
        int j  = tid + it * THREADS;    // 0..1791 = 128 imgs x 14 vec4
        int im = j / 14;
        int v  = j - im * 14;
        srcF[it] = im * 784 + v * 4;    // + r*56 per tile
        dstI[it] = v * NP + im;
    }

    // W (+ b) into shared
    {
        const float4* Wg = (const float4*)W;
        float4* Ws = (float4*)s_W;
        #pragma unroll 4
        for (int i = tid; i < W_FLOATS / 4; i += THREADS) Ws[i] = Wg[i];
        if (tid < 10) s_b[tid] = b[tid];
    }

    // prefetch tile 0 into registers
    float4 stage[7];
    #pragma unroll
    for (int it = 0; it < 7; it++)
        stage[it] = *(const float4*)(xg + srcF[it]);
    __syncthreads();    // W ready

    ull acc[10];
    #pragma unroll
    for (int o = 0; o < 10; o++) acc[o] = 0ull;

    #pragma unroll 1
    for (int r = 0; r < 14; r++) {
        // store staged tile (7 STS.128)
        #pragma unroll
        for (int it = 0; it < 7; it++) s_px[dstI[it]] = stage[it];
        __syncthreads();

        // prefetch next tile — LDG latency hidden behind the whole compute phase
        if (r < 13) {
            const float* srcT = xg + (r + 1) * 56;
            #pragma unroll
            for (int it = 0; it < 7; it++)
                stage[it] = *(const float4*)(srcT + srcF[it]);
        }

        if (chalf == 0) compute_tile<0>(s_px, s_W, r, img, acc);
        else            compute_tile<7>(s_px, s_W, r, img, acc);
        __syncthreads();
    }

    // reduce f32x2 lanes
    float sA[10];
    #pragma unroll
    for (int o = 0; o < 10; o++) {
        float2 a = unpack2(acc[o]);
        sA[o] = a.x + a.y;
    }

    // merge column-halves via shared (stride 11)
    if (chalf == 1) {
        #pragma unroll
        for (int o = 0; o < 10; o++) s_mg[img * 11 + o] = sA[o];
    }
    __syncthreads();

    if (chalf == 0) {
        float l[10];
        float m = -INFINITY;
        #pragma unroll
        for (int o = 0; o < 10; o++) {
            l[o] = sA[o] + s_mg[img * 11 + o] + s_b[o];
            m = fmaxf(m, l[o]);
        }
        float s = 0.f;
        #pragma unroll
        for (int o = 0; o < 10; o++) s += __expf(l[o] - m);
        float lse = m + __logf(s);
        float* op = out + (imgBase + img) * 10;
        #pragma unroll
        for (int o = 0; o < 10; o++) op[o] = l[o] - lse;
    }
}

extern "C" void kernel_launch(void* const* d_in, const int* in_sizes, int n_in,
                              void* d_out, int out_size)
{
    const float* x = (const float*)d_in[0];
    const float* W = (const float*)d_in[1];
    const float* b = (const float*)d_in[2];
    float* out = (float*)d_out;

    const int B = in_sizes[0] / 784;                  // 65536
    const int grid = B / IMGS;                        // 512
    const size_t smem = SMEM_FLOATS * sizeof(float);  // 60.3 KB

    cudaFuncSetAttribute(quanv_kernel,
                         cudaFuncAttributeMaxDynamicSharedMemorySize, (int)smem);
    quanv_kernel<<<grid, THREADS, smem>>>(x, W, b, out);
}

// round 8
// speedup vs baseline: 1.3858x; 1.0791x over previous
#include <cuda_runtime.h>
#include <math.h>
#include <stdint.h>

#define THREADS   128
#define IMGS      128          // images per block, 2 per thread
#define NP        129          // float4 stride per v-row (odd -> conflict-free)
#define PX_F4     (14 * NP)    // 1806 float4, single buffer
#define W_FLOATS  7840
#define SMEM_FLOATS (PX_F4 * 4 + W_FLOATS + 16)   // 15080 floats = 60.3 KB

typedef unsigned long long ull;

__device__ __forceinline__ void fma2(ull &acc, ull a, ull b) {
    asm("fma.rn.f32x2 %0, %1, %2, %0;" : "+l"(acc) : "l"(a), "l"(b));
}
__device__ __forceinline__ ull pack2(float lo, float hi) {
    ull r; asm("mov.b64 %0, {%1, %2};" : "=l"(r) : "f"(lo), "f"(hi)); return r;
}
__device__ __forceinline__ float2 unpack2(ull v) {
    float lo, hi; asm("mov.b64 {%0, %1}, %2;" : "=f"(lo), "=f"(hi) : "l"(v));
    return make_float2(lo, hi);
}

// one patch-row tile, two images (slots p and p+64), cols CB..CB+6
template<int CB>
__device__ __forceinline__ void compute_tile(const float4* __restrict__ px,
                                             const float*  __restrict__ s_W,
                                             int r, int p,
                                             ull* accA, ull* accB)
{
    const ulonglong2* wbase = (const ulonglong2*)s_W + r * 14;
    #pragma unroll
    for (int cc = 0; cc < 7; cc++) {
        const int c  = CB + cc;          // compile-time
        const int vA = c >> 1;           // float4 shared by cols 2vA, 2vA+1
        const int vB = 7 + vA;
        float4 a0 = px[vA * NP + p];         // img0, row 2r
        float4 a1 = px[vA * NP + 64 + p];    // img1, row 2r
        float4 b0 = px[vB * NP + p];         // img0, row 2r+1
        float4 b1 = px[vB * NP + 64 + p];    // img1, row 2r+1
        float x00_0, x01_0, x10_0, x11_0, x00_1, x01_1, x10_1, x11_1;
        if ((c & 1) == 0) {
            x00_0 = a0.x; x01_0 = a0.y; x10_0 = b0.x; x11_0 = b0.y;
            x00_1 = a1.x; x01_1 = a1.y; x10_1 = b1.x; x11_1 = b1.y;
        } else {
            x00_0 = a0.z; x01_0 = a0.w; x10_0 = b0.z; x11_0 = b0.w;
            x00_1 = a1.z; x01_1 = a1.w; x10_1 = b1.z; x11_1 = b1.w;
        }
        float e0a = __cosf(x00_0);
        float e1a = e0a * __cosf(x01_0);
        float e2a = e1a * __cosf(x10_0);
        float e3a = e2a * __cosf(x11_0);
        float e0b = __cosf(x00_1);
        float e1b = e0b * __cosf(x01_1);
        float e2b = e1b * __cosf(x10_1);
        float e3b = e2b * __cosf(x11_1);
        ull eA01 = pack2(e0a, e1a), eA23 = pack2(e2a, e3a);
        ull eB01 = pack2(e0b, e1b), eB23 = pack2(e2b, e3b);
        const ulonglong2* wrow = wbase + c;
        #pragma unroll
        for (int o = 0; o < 10; o++) {
            ulonglong2 w = wrow[o * 196];    // one uniform LDS.128 serves 2 images
            fma2(accA[o], eA01, w.x);
            fma2(accA[o], eA23, w.y);
            fma2(accB[o], eB01, w.x);
            fma2(accB[o], eB23, w.y);
        }
    }
}

__global__ void __launch_bounds__(THREADS, 3)
quanv_kernel(const float* __restrict__ x,
             const float* __restrict__ W,
             const float* __restrict__ b,
             float* __restrict__ out)
{
    extern __shared__ float smem[];
    float4* s_px = (float4*)smem;              // [14][NP] float4, single buffer
    float*  s_W  = smem + PX_F4 * 4;           // 7840 floats
    float*  s_b  = s_W + W_FLOATS;
    float*  s_mg = smem;                       // epilogue merge aliases px buffer

    const int tid   = threadIdx.x;
    const int p     = tid & 63;       // image-pair index (imgs 2p, 2p+1)
    const int chalf = tid >> 6;       // 0: cols 0..6, 1: cols 7..13 (warp-uniform)

    const long imgBase = (long)blockIdx.x * IMGS;
    const float* xg = x + imgBase * 784;

    // staging map (r-invariant): 14 float4 granules per thread
    int srcF[14], dstI[14];
    #pragma unroll
    for (int it = 0; it < 14; it++) {
        int j   = tid + it * THREADS;   // 0..1791 = 128 imgs x 14 vec4
        int img = j / 14;
        int v   = j - img * 14;
        int pos = ((img & 1) << 6) | (img >> 1);   // pair-split permutation
        srcF[it] = img * 784 + v * 4;   // + r*56 per tile
        dstI[it] = v * NP + pos;
    }

    // W (+ b) into shared
    {
        const float4* Wg = (const float4*)W;
        float4* Ws = (float4*)s_W;
        #pragma unroll 4
        for (int i = tid; i < W_FLOATS / 4; i += THREADS) Ws[i] = Wg[i];
        if (tid < 10) s_b[tid] = b[tid];
    }

    // prefetch tile 0 into registers
    float4 stage[14];
    #pragma unroll
    for (int it = 0; it < 14; it++)
        stage[it] = *(const float4*)(xg + srcF[it]);
    __syncthreads();    // W ready

    ull accA[10], accB[10];
    #pragma unroll
    for (int o = 0; o < 10; o++) { accA[o] = 0ull; accB[o] = 0ull; }

    #pragma unroll 1
    for (int r = 0; r < 14; r++) {
        // store staged tile (14 STS.128)
        #pragma unroll
        for (int it = 0; it < 14; it++) s_px[dstI[it]] = stage[it];
        __syncthreads();

        // prefetch next tile — LDG latency hidden behind compute
        if (r < 13) {
            const float* srcT = xg + (r + 1) * 56;
            #pragma unroll
            for (int it = 0; it < 14; it++)
                stage[it] = *(const float4*)(srcT + srcF[it]);
        }

        if (chalf == 0) compute_tile<0>(s_px, s_W, r, p, accA, accB);
        else            compute_tile<7>(s_px, s_W, r, p, accA, accB);
        __syncthreads();
    }

    // reduce f32x2 (even/odd k) lanes
    float sA[10], sB[10];
    #pragma unroll
    for (int o = 0; o < 10; o++) {
        float2 a = unpack2(accA[o]); sA[o] = a.x + a.y;
        float2 c = unpack2(accB[o]); sB[o] = c.x + c.y;
    }

    // merge the two column-halves via shared (stride 21 per image slot)
    if (chalf == 1) {
        #pragma unroll
        for (int o = 0; o < 10; o++) {
            s_mg[p * 42 + o]      = sA[o];
            s_mg[p * 42 + 21 + o] = sB[o];
        }
    }
    __syncthreads();

    if (chalf == 0) {
        float l[20];
        #pragma unroll
        for (int o = 0; o < 10; o++) {
            l[o]      = sA[o] + s_mg[p * 42 + o]      + s_b[o];
            l[10 + o] = sB[o] + s_mg[p * 42 + 21 + o] + s_b[o];
        }
        #pragma unroll
        for (int im = 0; im < 2; im++) {
            float m = -INFINITY;
            #pragma unroll
            for (int o = 0; o < 10; o++) m = fmaxf(m, l[im * 10 + o]);
            float s = 0.f;
            #pragma unroll
            for (int o = 0; o < 10; o++) s += __expf(l[im * 10 + o] - m);
            float lse = m + __logf(s);
            #pragma unroll
            for (int o = 0; o < 10; o++) l[im * 10 + o] -= lse;
        }
        float4* op = (float4*)(out + (imgBase + 2 * p) * 10);   // 20 floats, 16B aligned
        #pragma unroll
        for (int q = 0; q < 5; q++)
            op[q] = make_float4(l[q * 4], l[q * 4 + 1], l[q * 4 + 2], l[q * 4 + 3]);
    }
}

extern "C" void kernel_launch(void* const* d_in, const int* in_sizes, int n_in,
                              void* d_out, int out_size)
{
    const float* x = (const float*)d_in[0];
    const float* W = (const float*)d_in[1];
    const float* b = (const float*)d_in[2];
    float* out = (float*)d_out;

    const int B = in_sizes[0] / 784;                  // 65536
    const int grid = B / IMGS;                        // 512
    const size_t smem = SMEM_FLOATS * sizeof(float);  // 60.3 KB

    cudaFuncSetAttribute(quanv_kernel,
                         cudaFuncAttributeMaxDynamicSharedMemorySize, (int)smem);
    quanv_kernel<<<grid, THREADS, smem>>>(x, W, b, out);
}